// round 5
// baseline (speedup 1.0000x reference)
#include <cuda_runtime.h>
#include <cstdint>

#define GROUPS  2048
#define NT      16     // 16 b-tiles of 64 rows
#define S       68     // h smem row stride (words): conflict-free LDS.32 frag reads

__device__ __forceinline__ uint32_t f2tf32(float f) {
    uint32_t u; asm("cvt.rna.tf32.f32 %0, %1;" : "=r"(u) : "f"(f)); return u;
}

__device__ __forceinline__ void mma_tf32(float& d0, float& d1, float& d2, float& d3,
                                         uint32_t a0, uint32_t a1, uint32_t a2, uint32_t a3,
                                         uint32_t b0, uint32_t b1) {
    asm volatile("mma.sync.aligned.m16n8k8.row.col.f32.tf32.tf32.f32 "
                 "{%0,%1,%2,%3}, {%4,%5,%6,%7}, {%8,%9}, {%0,%1,%2,%3};"
                 : "+f"(d0), "+f"(d1), "+f"(d2), "+f"(d3)
                 : "r"(a0), "r"(a1), "r"(a2), "r"(a3), "r"(b0), "r"(b1));
}

// One CTA per group, 8 warps, warp tile m16 x n32 (4 m-subtiles x 2 j-halves).
// Both layers' weight frags + bias frags in registers. X A-frags loaded straight
// from global (L2-resident) with 1-iter register prefetch. h double-buffered in
// smem -> exactly ONE __syncthreads per 64-row iteration.
extern "C" __global__ void __launch_bounds__(256, 1) convnn_r5(
    const float* __restrict__ x,  const float* __restrict__ W0,
    const float* __restrict__ b0, const float* __restrict__ W1,
    const float* __restrict__ b1, float* __restrict__ out)
{
    __shared__ uint32_t hbuf[2][64 * S];

    const int g    = blockIdx.x;
    const int tid  = threadIdx.x;
    const int lane = tid & 31;
    const int warp = tid >> 5;
    const int gid  = lane >> 2;   // 0..7
    const int tig  = lane & 3;    // 0..3
    const int mrow = (warp & 3) * 16;
    const int jbase = (warp >> 2) * 32;

    // ---- stage weights through hbuf[0], pull this warp's frags into regs ----
    uint32_t wf[2][4][8][2];
    {
        const int sr = tid >> 2;          // 0..63
        const int sc = (tid & 3) << 4;    // 0,16,32,48
        #pragma unroll
        for (int layer = 0; layer < 2; layer++) {
            const float* W = (layer ? W1 : W0) + (size_t)g * 64 * 64;
            #pragma unroll
            for (int q = 0; q < 4; q++) {
                float4 w = *(const float4*)(W + (size_t)sr * 64 + sc + q * 4);
                uint32_t* d = &hbuf[0][sr * S + sc + q * 4];
                d[0] = f2tf32(w.x); d[1] = f2tf32(w.y);
                d[2] = f2tf32(w.z); d[3] = f2tf32(w.w);
            }
            __syncthreads();
            #pragma unroll
            for (int s = 0; s < 4; s++) {
                const int jr = (jbase + s * 8 + gid) * S;
                #pragma unroll
                for (int kc = 0; kc < 8; kc++) {
                    wf[layer][s][kc][0] = hbuf[0][jr + kc * 8 + tig];
                    wf[layer][s][kc][1] = hbuf[0][jr + kc * 8 + tig + 4];
                }
            }
            __syncthreads();
        }
    }

    // ---- bias fragments in registers ----
    float bf0[4][2], bf1[4][2];
    #pragma unroll
    for (int s = 0; s < 4; s++) {
        const int j = jbase + s * 8 + 2 * tig;
        bf0[s][0] = b0[(size_t)g * 64 + j];     bf0[s][1] = b0[(size_t)g * 64 + j + 1];
        bf1[s][0] = b1[(size_t)g * 64 + j];     bf1[s][1] = b1[(size_t)g * 64 + j + 1];
    }

    // row/col bases for direct-from-global X fragment loads
    const int r0 = mrow + gid;       // first frag row within tile
    // prefetch ax for tile 0
    uint32_t ax[8][4];
    {
        const float* xb = x + (size_t)r0 * 64;
        #pragma unroll
        for (int kc = 0; kc < 8; kc++) {
            const int k = kc * 8 + tig;
            ax[kc][0] = f2tf32(xb[k]);
            ax[kc][1] = f2tf32(xb[8 * 64 + k]);
            ax[kc][2] = f2tf32(xb[k + 4]);
            ax[kc][3] = f2tf32(xb[8 * 64 + k + 4]);
        }
    }

    for (int t = 0; t < NT; t++) {
        // ===== layer 0: acc = X(t) * W0^T  (A from regs) =====
        float acc[4][4];
        #pragma unroll
        for (int s = 0; s < 4; s++)
            #pragma unroll
            for (int i = 0; i < 4; i++) acc[s][i] = 0.f;
        #pragma unroll
        for (int kc = 0; kc < 8; kc++)
            #pragma unroll
            for (int s = 0; s < 4; s++)
                mma_tf32(acc[s][0], acc[s][1], acc[s][2], acc[s][3],
                         ax[kc][0], ax[kc][1], ax[kc][2], ax[kc][3],
                         wf[0][s][kc][0], wf[0][s][kc][1]);

        // epilogue 0: bias + LeakyReLU -> h into hbuf[t&1]
        uint32_t* hb = hbuf[t & 1];
        #pragma unroll
        for (int s = 0; s < 4; s++) {
            const int j = jbase + s * 8 + 2 * tig;
            float h00 = acc[s][0] + bf0[s][0]; h00 = (h00 > 0.f) ? h00 : 0.2f * h00;
            float h01 = acc[s][1] + bf0[s][1]; h01 = (h01 > 0.f) ? h01 : 0.2f * h01;
            float h10 = acc[s][2] + bf0[s][0]; h10 = (h10 > 0.f) ? h10 : 0.2f * h10;
            float h11 = acc[s][3] + bf0[s][1]; h11 = (h11 > 0.f) ? h11 : 0.2f * h11;
            *(uint2*)&hb[(r0)     * S + j] = make_uint2(f2tf32(h00), f2tf32(h01));
            *(uint2*)&hb[(r0 + 8) * S + j] = make_uint2(f2tf32(h10), f2tf32(h11));
        }

        // prefetch ax for tile t+1 (latency hides under sync + layer-1 phase)
        if (t + 1 < NT) {
            const float* xb = x + (size_t)((t + 1) * 64 + r0) * 64;
            #pragma unroll
            for (int kc = 0; kc < 8; kc++) {
                const int k = kc * 8 + tig;
                ax[kc][0] = f2tf32(xb[k]);
                ax[kc][1] = f2tf32(xb[8 * 64 + k]);
                ax[kc][2] = f2tf32(xb[k + 4]);
                ax[kc][3] = f2tf32(xb[8 * 64 + k + 4]);
            }
        }

        __syncthreads();   // h(t) visible; also fences h(t-1) reads vs h(t+1) writes

        // ===== layer 1: acc = h(t) * W1^T  (A frags via LDS) =====
        #pragma unroll
        for (int s = 0; s < 4; s++)
            #pragma unroll
            for (int i = 0; i < 4; i++) acc[s][i] = 0.f;
        #pragma unroll
        for (int kc = 0; kc < 8; kc++) {
            const int k0 = kc * 8;
            const uint32_t a0 = hb[(r0)     * S + k0 + tig];
            const uint32_t a1 = hb[(r0 + 8) * S + k0 + tig];
            const uint32_t a2 = hb[(r0)     * S + k0 + tig + 4];
            const uint32_t a3 = hb[(r0 + 8) * S + k0 + tig + 4];
            #pragma unroll
            for (int s = 0; s < 4; s++)
                mma_tf32(acc[s][0], acc[s][1], acc[s][2], acc[s][3],
                         a0, a1, a2, a3, wf[1][s][kc][0], wf[1][s][kc][1]);
        }

        // epilogue 1: bias, 32B-sector float2 stores
        const int brow = t * 64 + r0;
        #pragma unroll
        for (int s = 0; s < 4; s++) {
            const int j = jbase + s * 8 + 2 * tig;
            float2 v0 = make_float2(acc[s][0] + bf1[s][0], acc[s][1] + bf1[s][1]);
            float2 v1 = make_float2(acc[s][2] + bf1[s][0], acc[s][3] + bf1[s][1]);
            *(float2*)(out + ((size_t)brow       * GROUPS + g) * 64 + j) = v0;
            *(float2*)(out + ((size_t)(brow + 8) * GROUPS + g) * 64 + j) = v1;
        }
    }
}

extern "C" void kernel_launch(void* const* d_in, const int* in_sizes, int n_in,
                              void* d_out, int out_size) {
    const float* x  = (const float*)d_in[0];
    const float* W0 = (const float*)d_in[1];
    const float* b0 = (const float*)d_in[2];
    const float* W1 = (const float*)d_in[3];
    const float* b1 = (const float*)d_in[4];
    float* out = (float*)d_out;

    convnn_r5<<<GROUPS, 256>>>(x, W0, b0, W1, b1, out);
}

// round 6
// speedup vs baseline: 1.5274x; 1.5274x over previous
#include <cuda_runtime.h>
#include <cstdint>

#define GROUPS  2048
#define NT      16       // 16 b-tiles of 64 rows
#define S       68       // smem row stride (words): bank=(4*row+col)%32, conflict-free frags
#define SWORDS  (64*S)   // words per 64x64 buffer
#define SMEM_BYTES (4 * SWORDS * 4)   // X0,X1,H0,H1 = 69632 B

__device__ __forceinline__ uint32_t f2tf32(float f) {
    uint32_t u; asm("cvt.rna.tf32.f32 %0, %1;" : "=r"(u) : "f"(f)); return u;
}

__device__ __forceinline__ void mma_tf32(float& d0, float& d1, float& d2, float& d3,
                                         uint32_t a0, uint32_t a1, uint32_t a2, uint32_t a3,
                                         uint32_t b0, uint32_t b1) {
    asm volatile("mma.sync.aligned.m16n8k8.row.col.f32.tf32.tf32.f32 "
                 "{%0,%1,%2,%3}, {%4,%5,%6,%7}, {%8,%9}, {%0,%1,%2,%3};"
                 : "+f"(d0), "+f"(d1), "+f"(d2), "+f"(d3)
                 : "r"(a0), "r"(a1), "r"(a2), "r"(a3), "r"(b0), "r"(b1));
}

// One CTA per group, 128 threads (4 warps), 2 CTAs resident per SM.
// Warp tile m32 x n32: mrow=(warp&1)*32, jbase=(warp>>1)*32.
// Both layers' weight frags + bias frags in registers. X and h double-buffered
// in dynamic smem -> ONE __syncthreads per 64-row iteration.
extern "C" __global__ void __launch_bounds__(128, 2) convnn_r6(
    const float* __restrict__ x,  const float* __restrict__ W0,
    const float* __restrict__ b0, const float* __restrict__ W1,
    const float* __restrict__ b1, float* __restrict__ out)
{
    extern __shared__ uint32_t sm[];
    uint32_t* sX[2] = { sm,              sm + SWORDS     };
    uint32_t* sH[2] = { sm + 2*SWORDS,   sm + 3*SWORDS   };

    const int g    = blockIdx.x;
    const int tid  = threadIdx.x;
    const int lane = tid & 31;
    const int warp = tid >> 5;
    const int gid  = lane >> 2;   // 0..7
    const int tig  = lane & 3;    // 0..3
    const int mrow  = (warp & 1) * 32;
    const int jbase = (warp >> 1) * 32;
    const int r0    = mrow + gid;

    // ---- stage weights through sX[0], pull this warp's frags into regs ----
    uint32_t wf[2][4][8][2];   // [layer][j-subtile][k-chunk][2]
    #pragma unroll
    for (int layer = 0; layer < 2; layer++) {
        const float* W = (layer ? W1 : W0) + (size_t)g * 64 * 64;
        #pragma unroll
        for (int q = 0; q < 8; q++) {
            const int f   = q * 128 + tid;     // float4 index, coalesced
            const int row = f >> 4;
            const int c4  = (f & 15) << 2;
            float4 w = *(const float4*)(W + (size_t)row * 64 + c4);
            uint32_t* d = &sX[0][row * S + c4];
            d[0] = f2tf32(w.x); d[1] = f2tf32(w.y);
            d[2] = f2tf32(w.z); d[3] = f2tf32(w.w);
        }
        __syncthreads();
        #pragma unroll
        for (int s = 0; s < 4; s++) {
            const int jr = (jbase + s * 8 + gid) * S;
            #pragma unroll
            for (int kc = 0; kc < 8; kc++) {
                wf[layer][s][kc][0] = sX[0][jr + kc * 8 + tig];
                wf[layer][s][kc][1] = sX[0][jr + kc * 8 + tig + 4];
            }
        }
        __syncthreads();
    }

    // ---- bias fragments in registers ----
    float bf0[4][2], bf1[4][2];
    #pragma unroll
    for (int s = 0; s < 4; s++) {
        const int j = jbase + s * 8 + 2 * tig;
        bf0[s][0] = b0[(size_t)g * 64 + j]; bf0[s][1] = b0[(size_t)g * 64 + j + 1];
        bf1[s][0] = b1[(size_t)g * 64 + j]; bf1[s][1] = b1[(size_t)g * 64 + j + 1];
    }

    // ---- pre-loop: stage tile 0 into sX[0]; prefetch tile 1 ----
    float4 px[8];
    #pragma unroll
    for (int q = 0; q < 8; q++) {
        const int f = q * 128 + tid;
        float4 v = *(const float4*)(x + (size_t)f * 4);   // tile 0
        const int row = f >> 4, c4 = (f & 15) << 2;
        uint32_t* d = &sX[0][row * S + c4];
        d[0] = f2tf32(v.x); d[1] = f2tf32(v.y); d[2] = f2tf32(v.z); d[3] = f2tf32(v.w);
    }
    #pragma unroll
    for (int q = 0; q < 8; q++)
        px[q] = *(const float4*)(x + (size_t)4096 + (size_t)(q * 128 + tid) * 4);  // tile 1
    __syncthreads();

    for (int t = 0; t < NT; t++) {
        const uint32_t* Xb = sX[t & 1];
        uint32_t*       Hb = sH[t & 1];

        // ===== layer 0: acc = X(t) * W0^T =====
        float acc[4][2][4];   // [j-subtile][m-half][4]
        #pragma unroll
        for (int s = 0; s < 4; s++)
            #pragma unroll
            for (int m = 0; m < 2; m++)
                #pragma unroll
                for (int i = 0; i < 4; i++) acc[s][m][i] = 0.f;

        #pragma unroll
        for (int kc = 0; kc < 8; kc++) {
            const int k0 = kc * 8;
            uint32_t a[2][4];
            #pragma unroll
            for (int m = 0; m < 2; m++) {
                const int rr = r0 + m * 16;
                a[m][0] = Xb[(rr)     * S + k0 + tig];
                a[m][1] = Xb[(rr + 8) * S + k0 + tig];
                a[m][2] = Xb[(rr)     * S + k0 + tig + 4];
                a[m][3] = Xb[(rr + 8) * S + k0 + tig + 4];
            }
            #pragma unroll
            for (int s = 0; s < 4; s++)
                #pragma unroll
                for (int m = 0; m < 2; m++)
                    mma_tf32(acc[s][m][0], acc[s][m][1], acc[s][m][2], acc[s][m][3],
                             a[m][0], a[m][1], a[m][2], a[m][3],
                             wf[0][s][kc][0], wf[0][s][kc][1]);
        }

        // epilogue 0: bias + LeakyReLU -> h into sH[t&1]
        #pragma unroll
        for (int s = 0; s < 4; s++) {
            const int j = jbase + s * 8 + 2 * tig;
            #pragma unroll
            for (int m = 0; m < 2; m++) {
                const int rr = r0 + m * 16;
                float h00 = acc[s][m][0] + bf0[s][0]; h00 = (h00 > 0.f) ? h00 : 0.2f * h00;
                float h01 = acc[s][m][1] + bf0[s][1]; h01 = (h01 > 0.f) ? h01 : 0.2f * h01;
                float h10 = acc[s][m][2] + bf0[s][0]; h10 = (h10 > 0.f) ? h10 : 0.2f * h10;
                float h11 = acc[s][m][3] + bf0[s][1]; h11 = (h11 > 0.f) ? h11 : 0.2f * h11;
                *(uint2*)&Hb[(rr)     * S + j] = make_uint2(f2tf32(h00), f2tf32(h01));
                *(uint2*)&Hb[(rr + 8) * S + j] = make_uint2(f2tf32(h10), f2tf32(h11));
            }
        }

        // stage tile t+1 from px into sX[(t+1)&1]
        if (t + 1 < NT) {
            uint32_t* Xn = sX[(t + 1) & 1];
            #pragma unroll
            for (int q = 0; q < 8; q++) {
                const int f = q * 128 + tid;
                const int row = f >> 4, c4 = (f & 15) << 2;
                uint32_t* d = &Xn[row * S + c4];
                d[0] = f2tf32(px[q].x); d[1] = f2tf32(px[q].y);
                d[2] = f2tf32(px[q].z); d[3] = f2tf32(px[q].w);
            }
        }
        // prefetch tile t+2 (consumed at next iter's staging, after the sync)
        if (t + 2 < NT) {
            const float* xb = x + (size_t)(t + 2) * 4096;
            #pragma unroll
            for (int q = 0; q < 8; q++)
                px[q] = *(const float4*)(xb + (size_t)(q * 128 + tid) * 4);
        }

        __syncthreads();   // the only barrier per iteration

        // ===== layer 1: acc = h(t) * W1^T =====
        #pragma unroll
        for (int s = 0; s < 4; s++)
            #pragma unroll
            for (int m = 0; m < 2; m++)
                #pragma unroll
                for (int i = 0; i < 4; i++) acc[s][m][i] = 0.f;

        #pragma unroll
        for (int kc = 0; kc < 8; kc++) {
            const int k0 = kc * 8;
            uint32_t a[2][4];
            #pragma unroll
            for (int m = 0; m < 2; m++) {
                const int rr = r0 + m * 16;
                a[m][0] = Hb[(rr)     * S + k0 + tig];
                a[m][1] = Hb[(rr + 8) * S + k0 + tig];
                a[m][2] = Hb[(rr)     * S + k0 + tig + 4];
                a[m][3] = Hb[(rr + 8) * S + k0 + tig + 4];
            }
            #pragma unroll
            for (int s = 0; s < 4; s++)
                #pragma unroll
                for (int m = 0; m < 2; m++)
                    mma_tf32(acc[s][m][0], acc[s][m][1], acc[s][m][2], acc[s][m][3],
                             a[m][0], a[m][1], a[m][2], a[m][3],
                             wf[1][s][kc][0], wf[1][s][kc][1]);
        }

        // epilogue 1: bias, 32B-sector float2 stores
        #pragma unroll
        for (int s = 0; s < 4; s++) {
            const int j = jbase + s * 8 + 2 * tig;
            #pragma unroll
            for (int m = 0; m < 2; m++) {
                const int brow = t * 64 + r0 + m * 16;
                float2 v0 = make_float2(acc[s][m][0] + bf1[s][0], acc[s][m][1] + bf1[s][1]);
                float2 v1 = make_float2(acc[s][m][2] + bf1[s][0], acc[s][m][3] + bf1[s][1]);
                *(float2*)(out + ((size_t)brow       * GROUPS + g) * 64 + j) = v0;
                *(float2*)(out + ((size_t)(brow + 8) * GROUPS + g) * 64 + j) = v1;
            }
        }
    }
}

extern "C" void kernel_launch(void* const* d_in, const int* in_sizes, int n_in,
                              void* d_out, int out_size) {
    const float* x  = (const float*)d_in[0];
    const float* W0 = (const float*)d_in[1];
    const float* b0 = (const float*)d_in[2];
    const float* W1 = (const float*)d_in[3];
    const float* b1 = (const float*)d_in[4];
    float* out = (float*)d_out;

    cudaFuncSetAttribute(convnn_r6, cudaFuncAttributeMaxDynamicSharedMemorySize, SMEM_BYTES);
    convnn_r6<<<GROUPS, 128, SMEM_BYTES>>>(x, W0, b0, W1, b1, out);
}

// round 7
// speedup vs baseline: 1.5820x; 1.0358x over previous
#include <cuda_runtime.h>
#include <cstdint>

#define GROUPS  2048
#define NT      16
#define S       68                 // smem row stride (words)
#define SWORDS  (64 * S)           // one 64x64 buffer
#define SMEM_BYTES (4 * SWORDS * 4)  // X0,X1,H0,H1

__device__ __forceinline__ uint32_t f2tf32(float f) {
    uint32_t u; asm("cvt.rna.tf32.f32 %0, %1;" : "=r"(u) : "f"(f)); return u;
}
__device__ __forceinline__ uint32_t smem_u32(const void* p) {
    uint32_t a;
    asm("{ .reg .u64 t; cvta.to.shared.u64 t, %1; cvt.u32.u64 %0, t; }" : "=r"(a) : "l"(p));
    return a;
}
__device__ __forceinline__ void mma_tf32(float& d0, float& d1, float& d2, float& d3,
                                         uint32_t a0, uint32_t a1, uint32_t a2, uint32_t a3,
                                         uint32_t b0, uint32_t b1) {
    asm volatile("mma.sync.aligned.m16n8k8.row.col.f32.tf32.tf32.f32 "
                 "{%0,%1,%2,%3}, {%4,%5,%6,%7}, {%8,%9}, {%0,%1,%2,%3};"
                 : "+f"(d0), "+f"(d1), "+f"(d2), "+f"(d3)
                 : "r"(a0), "r"(a1), "r"(a2), "r"(a3), "r"(b0), "r"(b1));
}
__device__ __forceinline__ void ldm4(uint32_t& a0, uint32_t& a1, uint32_t& a2, uint32_t& a3,
                                     uint32_t sa) {
    asm volatile("ldmatrix.sync.aligned.m8n8.x4.shared.b16 {%0,%1,%2,%3}, [%4];"
                 : "=r"(a0), "=r"(a1), "=r"(a2), "=r"(a3) : "r"(sa));
}

// One CTA per group, 256 threads, 8 warps, warp tile m16 x n32.
// Weight + bias frags in registers. X and h double-buffered -> ONE barrier/iter.
// All A-fragments loaded via ldmatrix.x4 (1 instr per m16k8 frag).
extern "C" __global__ void __launch_bounds__(256, 1) convnn_r7(
    const float* __restrict__ x,  const float* __restrict__ W0,
    const float* __restrict__ b0, const float* __restrict__ W1,
    const float* __restrict__ b1, float* __restrict__ out)
{
    extern __shared__ uint32_t sm[];
    uint32_t* sX[2] = { sm,            sm + SWORDS };
    uint32_t* sH[2] = { sm + 2*SWORDS, sm + 3*SWORDS };
    const uint32_t sbase = smem_u32(sm);

    const int g    = blockIdx.x;
    const int tid  = threadIdx.x;
    const int lane = tid & 31;
    const int warp = tid >> 5;
    const int gid  = lane >> 2;
    const int tig  = lane & 3;
    const int mrow  = (warp & 3) * 16;
    const int jbase = (warp >> 2) * 32;
    const int r0    = mrow + gid;

    // per-lane ldmatrix row-address offset (words): matrix m=lane/8, row=lane%7
    const uint32_t fragwoff =
        (uint32_t)((mrow + ((lane >> 3) & 1) * 8 + (lane & 7)) * S + (lane >> 4) * 4);

    // ---- stage weights through sX[0]; pull this warp's B-frags into regs ----
    uint32_t wf[2][4][8][2];
    #pragma unroll
    for (int layer = 0; layer < 2; layer++) {
        const float* W = (layer ? W1 : W0) + (size_t)g * 64 * 64;
        #pragma unroll
        for (int q = 0; q < 4; q++) {
            const int f   = q * 256 + tid;      // float4 idx, coalesced
            const int row = f >> 4;
            const int c4  = (f & 15) << 2;
            float4 w = *(const float4*)(W + (size_t)row * 64 + c4);
            uint32_t* d = &sX[0][row * S + c4];
            d[0] = f2tf32(w.x); d[1] = f2tf32(w.y);
            d[2] = f2tf32(w.z); d[3] = f2tf32(w.w);
        }
        __syncthreads();
        #pragma unroll
        for (int s = 0; s < 4; s++) {
            const int jr = (jbase + s * 8 + gid) * S;
            #pragma unroll
            for (int kc = 0; kc < 8; kc++) {
                wf[layer][s][kc][0] = sX[0][jr + kc * 8 + tig];
                wf[layer][s][kc][1] = sX[0][jr + kc * 8 + tig + 4];
            }
        }
        __syncthreads();
    }

    // ---- bias fragments ----
    float bf0[4][2], bf1[4][2];
    #pragma unroll
    for (int s = 0; s < 4; s++) {
        const int j = jbase + s * 8 + 2 * tig;
        bf0[s][0] = b0[(size_t)g * 64 + j]; bf0[s][1] = b0[(size_t)g * 64 + j + 1];
        bf1[s][0] = b1[(size_t)g * 64 + j]; bf1[s][1] = b1[(size_t)g * 64 + j + 1];
    }

    // ---- stage tile 0; prefetch tile 1 ----
    #pragma unroll
    for (int q = 0; q < 4; q++) {
        const int f = q * 256 + tid;
        float4 v = *(const float4*)(x + (size_t)f * 4);
        const int row = f >> 4, c4 = (f & 15) << 2;
        uint32_t* d = &sX[0][row * S + c4];
        d[0] = f2tf32(v.x); d[1] = f2tf32(v.y); d[2] = f2tf32(v.z); d[3] = f2tf32(v.w);
    }
    float4 px[4];
    #pragma unroll
    for (int q = 0; q < 4; q++)
        px[q] = *(const float4*)(x + (size_t)4096 + (size_t)(q * 256 + tid) * 4);
    __syncthreads();

    for (int t = 0; t < NT; t++) {
        const uint32_t xb = sbase + (uint32_t)((t & 1) ? SWORDS : 0) * 4;
        const uint32_t hbA = sbase + (uint32_t)(2 + (t & 1)) * SWORDS * 4;
        uint32_t* Hb = sH[t & 1];

        // ===== layer 0: acc = X(t) * W0^T  (A via ldmatrix.x4) =====
        float acc[4][4];
        #pragma unroll
        for (int s = 0; s < 4; s++)
            #pragma unroll
            for (int i = 0; i < 4; i++) acc[s][i] = 0.f;

        #pragma unroll
        for (int kc = 0; kc < 8; kc++) {
            uint32_t a0, a1, a2, a3;
            ldm4(a0, a1, a2, a3, xb + (fragwoff + kc * 8) * 4);
            #pragma unroll
            for (int s = 0; s < 4; s++)
                mma_tf32(acc[s][0], acc[s][1], acc[s][2], acc[s][3],
                         a0, a1, a2, a3, wf[0][s][kc][0], wf[0][s][kc][1]);
        }

        // epilogue 0: bias + LeakyReLU -> h into sH[t&1]
        #pragma unroll
        for (int s = 0; s < 4; s++) {
            const int j = jbase + s * 8 + 2 * tig;
            float h00 = acc[s][0] + bf0[s][0]; h00 = (h00 > 0.f) ? h00 : 0.2f * h00;
            float h01 = acc[s][1] + bf0[s][1]; h01 = (h01 > 0.f) ? h01 : 0.2f * h01;
            float h10 = acc[s][2] + bf0[s][0]; h10 = (h10 > 0.f) ? h10 : 0.2f * h10;
            float h11 = acc[s][3] + bf0[s][1]; h11 = (h11 > 0.f) ? h11 : 0.2f * h11;
            *(uint2*)&Hb[(r0)     * S + j] = make_uint2(f2tf32(h00), f2tf32(h01));
            *(uint2*)&Hb[(r0 + 8) * S + j] = make_uint2(f2tf32(h10), f2tf32(h11));
        }

        // stage tile t+1 into the other X buffer; prefetch tile t+2
        if (t + 1 < NT) {
            uint32_t* Xn = sX[(t + 1) & 1];
            #pragma unroll
            for (int q = 0; q < 4; q++) {
                const int f = q * 256 + tid;
                const int row = f >> 4, c4 = (f & 15) << 2;
                uint32_t* d = &Xn[row * S + c4];
                d[0] = f2tf32(px[q].x); d[1] = f2tf32(px[q].y);
                d[2] = f2tf32(px[q].z); d[3] = f2tf32(px[q].w);
            }
        }
        if (t + 2 < NT) {
            const float* xsrc = x + (size_t)(t + 2) * 4096;
            #pragma unroll
            for (int q = 0; q < 4; q++)
                px[q] = *(const float4*)(xsrc + (size_t)(q * 256 + tid) * 4);
        }

        __syncthreads();   // the only barrier per iteration

        // ===== layer 1: acc = h(t) * W1^T  (A via ldmatrix.x4) =====
        #pragma unroll
        for (int s = 0; s < 4; s++)
            #pragma unroll
            for (int i = 0; i < 4; i++) acc[s][i] = 0.f;

        #pragma unroll
        for (int kc = 0; kc < 8; kc++) {
            uint32_t a0, a1, a2, a3;
            ldm4(a0, a1, a2, a3, hbA + (fragwoff + kc * 8) * 4);
            #pragma unroll
            for (int s = 0; s < 4; s++)
                mma_tf32(acc[s][0], acc[s][1], acc[s][2], acc[s][3],
                         a0, a1, a2, a3, wf[1][s][kc][0], wf[1][s][kc][1]);
        }

        // epilogue 1: bias, 32B-sector float2 stores
        const int brow = t * 64 + r0;
        #pragma unroll
        for (int s = 0; s < 4; s++) {
            const int j = jbase + s * 8 + 2 * tig;
            float2 v0 = make_float2(acc[s][0] + bf1[s][0], acc[s][1] + bf1[s][1]);
            float2 v1 = make_float2(acc[s][2] + bf1[s][0], acc[s][3] + bf1[s][1]);
            *(float2*)(out + ((size_t)brow       * GROUPS + g) * 64 + j) = v0;
            *(float2*)(out + ((size_t)(brow + 8) * GROUPS + g) * 64 + j) = v1;
        }
    }
}

extern "C" void kernel_launch(void* const* d_in, const int* in_sizes, int n_in,
                              void* d_out, int out_size) {
    const float* x  = (const float*)d_in[0];
    const float* W0 = (const float*)d_in[1];
    const float* b0 = (const float*)d_in[2];
    const float* W1 = (const float*)d_in[3];
    const float* b1 = (const float*)d_in[4];
    float* out = (float*)d_out;

    cudaFuncSetAttribute(convnn_r7, cudaFuncAttributeMaxDynamicSharedMemorySize, SMEM_BYTES);
    convnn_r7<<<GROUPS, 256, SMEM_BYTES>>>(x, W0, b0, W1, b1, out);
}

// round 8
// speedup vs baseline: 2.5668x; 1.6225x over previous
#include <cuda_runtime.h>
#include <cuda_fp16.h>
#include <cstdint>

#define GROUPS  2048
#define NT      16
#define SW      36    // smem row stride in 32-bit words (= 72 halves = 144 B, 16B-aligned)

__device__ __forceinline__ uint32_t pack2h(float lo, float hi) {
    __half2 h = __floats2half2_rn(lo, hi);   // lo -> lower 16 bits (first in memory)
    return *reinterpret_cast<uint32_t*>(&h);
}

__device__ __forceinline__ void mma_f16(float& d0, float& d1, float& d2, float& d3,
                                        uint32_t a0, uint32_t a1, uint32_t a2, uint32_t a3,
                                        uint32_t b0, uint32_t b1) {
    asm volatile("mma.sync.aligned.m16n8k16.row.col.f32.f16.f16.f32 "
                 "{%0,%1,%2,%3}, {%4,%5,%6,%7}, {%8,%9}, {%0,%1,%2,%3};"
                 : "+f"(d0), "+f"(d1), "+f"(d2), "+f"(d3)
                 : "r"(a0), "r"(a1), "r"(a2), "r"(a3), "r"(b0), "r"(b1));
}

// R2 structure, fp16 operands. One CTA per group, 256 threads, 8 warps,
// warp tile m16 x n32. Both layers' weight frags (64 regs) + biases in
// registers; X staged / h round-trip through one smem buffer (fp16).
extern "C" __global__ void __launch_bounds__(256, 1) convnn_r8(
    const float* __restrict__ x,  const float* __restrict__ W0,
    const float* __restrict__ b0, const float* __restrict__ W1,
    const float* __restrict__ b1, float* __restrict__ out)
{
    __shared__ uint32_t sbuf[64 * SW];   // 64 rows x 72 halves (word-addressed)

    const int g    = blockIdx.x;
    const int tid  = threadIdx.x;
    const int lane = tid & 31;
    const int warp = tid >> 5;
    const int gid  = lane >> 2;   // 0..7
    const int tig  = lane & 3;    // 0..3
    const int mrow  = (warp & 3) * 16;
    const int jbase = (warp >> 2) * 32;
    const int r0    = mrow + gid;

    const int sr = tid >> 4;          // staging row 0..15 (+16*rr)
    const int c4 = (tid & 15) << 2;   // staging col base (floats)

    // ---- stage W0/W1 (fp16) through sbuf, pull this warp's B-frags ----
    // b-frag for (s,kc): j = jbase + s*8 + gid;
    //   b0 = halves (k = kc*16 + 2*tig, +1), b1 = (k = kc*16 + 8 + 2*tig, +1)
    uint32_t wf[2][4][4][2];
    #pragma unroll
    for (int layer = 0; layer < 2; layer++) {
        const float* W = (layer ? W1 : W0) + (size_t)g * 64 * 64;
        #pragma unroll
        for (int rr = 0; rr < 4; rr++) {
            const int row = sr + rr * 16;
            float4 w = *(const float4*)(W + (size_t)row * 64 + c4);
            *(uint2*)&sbuf[row * SW + (c4 >> 1)] =
                make_uint2(pack2h(w.x, w.y), pack2h(w.z, w.w));
        }
        __syncthreads();
        #pragma unroll
        for (int s = 0; s < 4; s++) {
            const int jr = (jbase + s * 8 + gid) * SW;
            #pragma unroll
            for (int kc = 0; kc < 4; kc++) {
                wf[layer][s][kc][0] = sbuf[jr + kc * 8 + tig];
                wf[layer][s][kc][1] = sbuf[jr + kc * 8 + 4 + tig];
            }
        }
        __syncthreads();
    }

    // ---- bias fragments (fp32) ----
    float bf0[4][2], bf1[4][2];
    #pragma unroll
    for (int s = 0; s < 4; s++) {
        const int j = jbase + s * 8 + 2 * tig;
        bf0[s][0] = b0[(size_t)g * 64 + j]; bf0[s][1] = b0[(size_t)g * 64 + j + 1];
        bf1[s][0] = b1[(size_t)g * 64 + j]; bf1[s][1] = b1[(size_t)g * 64 + j + 1];
    }

    // ---- prefetch first X tile ----
    float4 px[4];
    #pragma unroll
    for (int rr = 0; rr < 4; rr++)
        px[rr] = *(const float4*)(x + (size_t)(sr + rr * 16) * 64 + c4);

    for (int it = 0; it < NT; it++) {
        // store X tile (fp16)
        #pragma unroll
        for (int rr = 0; rr < 4; rr++) {
            const int row = sr + rr * 16;
            *(uint2*)&sbuf[row * SW + (c4 >> 1)] =
                make_uint2(pack2h(px[rr].x, px[rr].y), pack2h(px[rr].z, px[rr].w));
        }
        __syncthreads();

        // prefetch next tile
        if (it + 1 < NT) {
            const float* xs = x + (size_t)(it + 1) * 4096;
            #pragma unroll
            for (int rr = 0; rr < 4; rr++)
                px[rr] = *(const float4*)(xs + (size_t)(sr + rr * 16) * 64 + c4);
        }

        float acc[4][4];
        #pragma unroll
        for (int s = 0; s < 4; s++)
            #pragma unroll
            for (int i = 0; i < 4; i++) acc[s][i] = 0.f;

        // ===== layer 0: acc = X * W0^T (4 k-chunks of 16) =====
        #pragma unroll
        for (int kc = 0; kc < 4; kc++) {
            const int kw = kc * 8 + tig;   // word offset of halves (2*tig within chunk)
            const uint32_t a0 = sbuf[(r0)     * SW + kw];
            const uint32_t a1 = sbuf[(r0 + 8) * SW + kw];
            const uint32_t a2 = sbuf[(r0)     * SW + kw + 4];
            const uint32_t a3 = sbuf[(r0 + 8) * SW + kw + 4];
            #pragma unroll
            for (int s = 0; s < 4; s++)
                mma_f16(acc[s][0], acc[s][1], acc[s][2], acc[s][3],
                        a0, a1, a2, a3, wf[0][s][kc][0], wf[0][s][kc][1]);
        }
        __syncthreads();   // X reads done before h overwrites

        // epilogue 0: bias + LeakyReLU -> h (fp16) into sbuf
        #pragma unroll
        for (int s = 0; s < 4; s++) {
            const int jw = (jbase >> 1) + s * 4 + tig;   // word index of col pair
            float h00 = acc[s][0] + bf0[s][0]; h00 = (h00 > 0.f) ? h00 : 0.2f * h00;
            float h01 = acc[s][1] + bf0[s][1]; h01 = (h01 > 0.f) ? h01 : 0.2f * h01;
            float h10 = acc[s][2] + bf0[s][0]; h10 = (h10 > 0.f) ? h10 : 0.2f * h10;
            float h11 = acc[s][3] + bf0[s][1]; h11 = (h11 > 0.f) ? h11 : 0.2f * h11;
            sbuf[(r0)     * SW + jw] = pack2h(h00, h01);
            sbuf[(r0 + 8) * SW + jw] = pack2h(h10, h11);
        }
        __syncthreads();   // h visible

        // ===== layer 1: acc = h * W1^T =====
        #pragma unroll
        for (int s = 0; s < 4; s++)
            #pragma unroll
            for (int i = 0; i < 4; i++) acc[s][i] = 0.f;

        #pragma unroll
        for (int kc = 0; kc < 4; kc++) {
            const int kw = kc * 8 + tig;
            const uint32_t a0 = sbuf[(r0)     * SW + kw];
            const uint32_t a1 = sbuf[(r0 + 8) * SW + kw];
            const uint32_t a2 = sbuf[(r0)     * SW + kw + 4];
            const uint32_t a3 = sbuf[(r0 + 8) * SW + kw + 4];
            #pragma unroll
            for (int s = 0; s < 4; s++)
                mma_f16(acc[s][0], acc[s][1], acc[s][2], acc[s][3],
                        a0, a1, a2, a3, wf[1][s][kc][0], wf[1][s][kc][1]);
        }
        __syncthreads();   // h reads done before next iter's X store

        // epilogue 1: bias, 32B-sector float2 stores
        const int brow = it * 64 + r0;
        #pragma unroll
        for (int s = 0; s < 4; s++) {
            const int j = jbase + s * 8 + 2 * tig;
            float2 v0 = make_float2(acc[s][0] + bf1[s][0], acc[s][1] + bf1[s][1]);
            float2 v1 = make_float2(acc[s][2] + bf1[s][0], acc[s][3] + bf1[s][1]);
            *(float2*)(out + ((size_t)brow       * GROUPS + g) * 64 + j) = v0;
            *(float2*)(out + ((size_t)(brow + 8) * GROUPS + g) * 64 + j) = v1;
        }
    }
}

extern "C" void kernel_launch(void* const* d_in, const int* in_sizes, int n_in,
                              void* d_out, int out_size) {
    const float* x  = (const float*)d_in[0];
    const float* W0 = (const float*)d_in[1];
    const float* b0 = (const float*)d_in[2];
    const float* W1 = (const float*)d_in[3];
    const float* b1 = (const float*)d_in[4];
    float* out = (float*)d_out;

    convnn_r8<<<GROUPS, 256>>>(x, W0, b0, W1, b1, out);
}

// round 9
// speedup vs baseline: 2.8471x; 1.1092x over previous
#include <cuda_runtime.h>
#include <cuda_fp16.h>
#include <cstdint>

#define GROUPS  2048
#define NT      16
#define SW      36    // smem row stride in 32-bit words (= 72 halves = 144 B)

__device__ __forceinline__ uint32_t pack2h(float lo, float hi) {
    __half2 h = __floats2half2_rn(lo, hi);
    return *reinterpret_cast<uint32_t*>(&h);
}

__device__ __forceinline__ void mma_f16(float& d0, float& d1, float& d2, float& d3,
                                        uint32_t a0, uint32_t a1, uint32_t a2, uint32_t a3,
                                        uint32_t b0, uint32_t b1) {
    asm volatile("mma.sync.aligned.m16n8k16.row.col.f32.f16.f16.f32 "
                 "{%0,%1,%2,%3}, {%4,%5,%6,%7}, {%8,%9}, {%0,%1,%2,%3};"
                 : "+f"(d0), "+f"(d1), "+f"(d2), "+f"(d3)
                 : "r"(a0), "r"(a1), "r"(a2), "r"(a3), "r"(b0), "r"(b1));
}

// fp16 R8 structure with 2 CTAs/SM. One CTA per group, 256 threads, 8 warps,
// warp tile m16 x n32, both layers' weight frags in regs, h round-trip in smem.
// Register budget trimmed (prefetch pre-packed to half2) to fit the 128-reg cap.
extern "C" __global__ void __launch_bounds__(256, 2) convnn_r9(
    const float* __restrict__ x,  const float* __restrict__ W0,
    const float* __restrict__ b0, const float* __restrict__ W1,
    const float* __restrict__ b1, float* __restrict__ out)
{
    __shared__ uint32_t sbuf[64 * SW];

    const int g    = blockIdx.x;
    const int tid  = threadIdx.x;
    const int lane = tid & 31;
    const int warp = tid >> 5;
    const int gid  = lane >> 2;
    const int tig  = lane & 3;
    const int mrow  = (warp & 3) * 16;
    const int jbase = (warp >> 2) * 32;
    const int r0    = mrow + gid;

    const int sr = tid >> 4;          // staging row 0..15 (+16*rr)
    const int c4 = (tid & 15) << 2;   // staging col base (floats)

    // ---- stage W0/W1 (fp16) through sbuf, pull this warp's B-frags ----
    uint32_t wf[2][4][4][2];
    #pragma unroll
    for (int layer = 0; layer < 2; layer++) {
        const float* W = (layer ? W1 : W0) + (size_t)g * 64 * 64;
        #pragma unroll
        for (int rr = 0; rr < 4; rr++) {
            const int row = sr + rr * 16;
            float4 w = *(const float4*)(W + (size_t)row * 64 + c4);
            *(uint2*)&sbuf[row * SW + (c4 >> 1)] =
                make_uint2(pack2h(w.x, w.y), pack2h(w.z, w.w));
        }
        __syncthreads();
        #pragma unroll
        for (int s = 0; s < 4; s++) {
            const int jr = (jbase + s * 8 + gid) * SW;
            #pragma unroll
            for (int kc = 0; kc < 4; kc++) {
                wf[layer][s][kc][0] = sbuf[jr + kc * 8 + tig];
                wf[layer][s][kc][1] = sbuf[jr + kc * 8 + 4 + tig];
            }
        }
        __syncthreads();
    }

    // ---- bias fragments (fp32) ----
    float bf0[4][2], bf1[4][2];
    #pragma unroll
    for (int s = 0; s < 4; s++) {
        const int j = jbase + s * 8 + 2 * tig;
        bf0[s][0] = b0[(size_t)g * 64 + j]; bf0[s][1] = b0[(size_t)g * 64 + j + 1];
        bf1[s][0] = b1[(size_t)g * 64 + j]; bf1[s][1] = b1[(size_t)g * 64 + j + 1];
    }

    // ---- prefetch first X tile, pre-packed to half2 (8 regs) ----
    uint2 px[4];
    #pragma unroll
    for (int rr = 0; rr < 4; rr++) {
        float4 v = *(const float4*)(x + (size_t)(sr + rr * 16) * 64 + c4);
        px[rr] = make_uint2(pack2h(v.x, v.y), pack2h(v.z, v.w));
    }

    for (int it = 0; it < NT; it++) {
        // store X tile (fp16)
        #pragma unroll
        for (int rr = 0; rr < 4; rr++)
            *(uint2*)&sbuf[(sr + rr * 16) * SW + (c4 >> 1)] = px[rr];
        __syncthreads();

        // prefetch next tile (pre-packed)
        if (it + 1 < NT) {
            const float* xs = x + (size_t)(it + 1) * 4096;
            #pragma unroll
            for (int rr = 0; rr < 4; rr++) {
                float4 v = *(const float4*)(xs + (size_t)(sr + rr * 16) * 64 + c4);
                px[rr] = make_uint2(pack2h(v.x, v.y), pack2h(v.z, v.w));
            }
        }

        float acc[4][4];
        #pragma unroll
        for (int s = 0; s < 4; s++)
            #pragma unroll
            for (int i = 0; i < 4; i++) acc[s][i] = 0.f;

        // ===== layer 0: acc = X * W0^T (4 k-chunks of 16) =====
        #pragma unroll
        for (int kc = 0; kc < 4; kc++) {
            const int kw = kc * 8 + tig;
            const uint32_t a0 = sbuf[(r0)     * SW + kw];
            const uint32_t a1 = sbuf[(r0 + 8) * SW + kw];
            const uint32_t a2 = sbuf[(r0)     * SW + kw + 4];
            const uint32_t a3 = sbuf[(r0 + 8) * SW + kw + 4];
            #pragma unroll
            for (int s = 0; s < 4; s++)
                mma_f16(acc[s][0], acc[s][1], acc[s][2], acc[s][3],
                        a0, a1, a2, a3, wf[0][s][kc][0], wf[0][s][kc][1]);
        }
        __syncthreads();   // X reads done before h overwrites

        // epilogue 0: bias + LeakyReLU -> h (fp16) into sbuf
        #pragma unroll
        for (int s = 0; s < 4; s++) {
            const int jw = (jbase >> 1) + s * 4 + tig;
            float h00 = acc[s][0] + bf0[s][0]; h00 = (h00 > 0.f) ? h00 : 0.2f * h00;
            float h01 = acc[s][1] + bf0[s][1]; h01 = (h01 > 0.f) ? h01 : 0.2f * h01;
            float h10 = acc[s][2] + bf0[s][0]; h10 = (h10 > 0.f) ? h10 : 0.2f * h10;
            float h11 = acc[s][3] + bf0[s][1]; h11 = (h11 > 0.f) ? h11 : 0.2f * h11;
            sbuf[(r0)     * SW + jw] = pack2h(h00, h01);
            sbuf[(r0 + 8) * SW + jw] = pack2h(h10, h11);
        }
        __syncthreads();   // h visible

        // ===== layer 1: acc = h * W1^T =====
        #pragma unroll
        for (int s = 0; s < 4; s++)
            #pragma unroll
            for (int i = 0; i < 4; i++) acc[s][i] = 0.f;

        #pragma unroll
        for (int kc = 0; kc < 4; kc++) {
            const int kw = kc * 8 + tig;
            const uint32_t a0 = sbuf[(r0)     * SW + kw];
            const uint32_t a1 = sbuf[(r0 + 8) * SW + kw];
            const uint32_t a2 = sbuf[(r0)     * SW + kw + 4];
            const uint32_t a3 = sbuf[(r0 + 8) * SW + kw + 4];
            #pragma unroll
            for (int s = 0; s < 4; s++)
                mma_f16(acc[s][0], acc[s][1], acc[s][2], acc[s][3],
                        a0, a1, a2, a3, wf[1][s][kc][0], wf[1][s][kc][1]);
        }
        __syncthreads();   // h reads done before next iter's X store

        // epilogue 1: bias, 32B-sector float2 stores
        const int brow = it * 64 + r0;
        #pragma unroll
        for (int s = 0; s < 4; s++) {
            const int j = jbase + s * 8 + 2 * tig;
            float2 v0 = make_float2(acc[s][0] + bf1[s][0], acc[s][1] + bf1[s][1]);
            float2 v1 = make_float2(acc[s][2] + bf1[s][0], acc[s][3] + bf1[s][1]);
            *(float2*)(out + ((size_t)brow       * GROUPS + g) * 64 + j) = v0;
            *(float2*)(out + ((size_t)(brow + 8) * GROUPS + g) * 64 + j) = v1;
        }
    }
}

extern "C" void kernel_launch(void* const* d_in, const int* in_sizes, int n_in,
                              void* d_out, int out_size) {
    const float* x  = (const float*)d_in[0];
    const float* W0 = (const float*)d_in[1];
    const float* b0 = (const float*)d_in[2];
    const float* W1 = (const float*)d_in[3];
    const float* b1 = (const float*)d_in[4];
    float* out = (float*)d_out;

    convnn_r9<<<GROUPS, 256>>>(x, W0, b0, W1, b1, out);
}

// round 10
// speedup vs baseline: 2.8892x; 1.0148x over previous
#include <cuda_runtime.h>
#include <cuda_fp16.h>
#include <cstdint>

#define GROUPS  2048
#define NT      16
#define SW      36    // smem row stride in 32-bit words (= 72 halves = 144 B)

__device__ __forceinline__ uint32_t pack2h(float lo, float hi) {
    __half2 h = __floats2half2_rn(lo, hi);
    return *reinterpret_cast<uint32_t*>(&h);
}

__device__ __forceinline__ void mma_f16(float& d0, float& d1, float& d2, float& d3,
                                        uint32_t a0, uint32_t a1, uint32_t a2, uint32_t a3,
                                        uint32_t b0, uint32_t b1) {
    asm volatile("mma.sync.aligned.m16n8k16.row.col.f32.f16.f16.f32 "
                 "{%0,%1,%2,%3}, {%4,%5,%6,%7}, {%8,%9}, {%0,%1,%2,%3};"
                 : "+f"(d0), "+f"(d1), "+f"(d2), "+f"(d3)
                 : "r"(a0), "r"(a1), "r"(a2), "r"(a3), "r"(b0), "r"(b1));
}

// fp16, 2 CTAs/SM, one CTA per group, 256 threads, warp tile m16 x n32.
// Separate X and H smem buffers -> exactly TWO __syncthreads per iteration:
//   bar1: X(t) visible   (also orders L1(t-1) h-reads before epi0(t) h-writes)
//   bar2: h(t) visible   (also orders L0(t) X-reads before storeX(t+1))
extern "C" __global__ void __launch_bounds__(256, 2) convnn_r10(
    const float* __restrict__ x,  const float* __restrict__ W0,
    const float* __restrict__ b0, const float* __restrict__ W1,
    const float* __restrict__ b1, float* __restrict__ out)
{
    __shared__ uint32_t sX[64 * SW];
    __shared__ uint32_t sH[64 * SW];

    const int g    = blockIdx.x;
    const int tid  = threadIdx.x;
    const int lane = tid & 31;
    const int warp = tid >> 5;
    const int gid  = lane >> 2;
    const int tig  = lane & 3;
    const int mrow  = (warp & 3) * 16;
    const int jbase = (warp >> 2) * 32;
    const int r0    = mrow + gid;

    const int sr = tid >> 4;          // staging row 0..15 (+16*rr)
    const int c4 = (tid & 15) << 2;   // staging col base (floats)

    // ---- stage W0/W1 (fp16) through sX, pull this warp's B-frags ----
    uint32_t wf[2][4][4][2];
    #pragma unroll
    for (int layer = 0; layer < 2; layer++) {
        const float* W = (layer ? W1 : W0) + (size_t)g * 64 * 64;
        #pragma unroll
        for (int rr = 0; rr < 4; rr++) {
            const int row = sr + rr * 16;
            float4 w = *(const float4*)(W + (size_t)row * 64 + c4);
            *(uint2*)&sX[row * SW + (c4 >> 1)] =
                make_uint2(pack2h(w.x, w.y), pack2h(w.z, w.w));
        }
        __syncthreads();
        #pragma unroll
        for (int s = 0; s < 4; s++) {
            const int jr = (jbase + s * 8 + gid) * SW;
            #pragma unroll
            for (int kc = 0; kc < 4; kc++) {
                wf[layer][s][kc][0] = sX[jr + kc * 8 + tig];
                wf[layer][s][kc][1] = sX[jr + kc * 8 + 4 + tig];
            }
        }
        __syncthreads();
    }

    // ---- bias fragments (fp32) ----
    float bf0[4][2], bf1[4][2];
    #pragma unroll
    for (int s = 0; s < 4; s++) {
        const int j = jbase + s * 8 + 2 * tig;
        bf0[s][0] = b0[(size_t)g * 64 + j]; bf0[s][1] = b0[(size_t)g * 64 + j + 1];
        bf1[s][0] = b1[(size_t)g * 64 + j]; bf1[s][1] = b1[(size_t)g * 64 + j + 1];
    }

    // ---- prefetch first X tile, pre-packed to half2 ----
    uint2 px[4];
    #pragma unroll
    for (int rr = 0; rr < 4; rr++) {
        float4 v = *(const float4*)(x + (size_t)(sr + rr * 16) * 64 + c4);
        px[rr] = make_uint2(pack2h(v.x, v.y), pack2h(v.z, v.w));
    }

    for (int it = 0; it < NT; it++) {
        // store X tile (fp16) -- safe: all L0(t-1) X reads finished before bar2(t-1)
        #pragma unroll
        for (int rr = 0; rr < 4; rr++)
            *(uint2*)&sX[(sr + rr * 16) * SW + (c4 >> 1)] = px[rr];
        __syncthreads();   // bar1: X visible; L1(t-1) h-reads < epi0(t) h-writes

        // prefetch next tile (pre-packed)
        if (it + 1 < NT) {
            const float* xs = x + (size_t)(it + 1) * 4096;
            #pragma unroll
            for (int rr = 0; rr < 4; rr++) {
                float4 v = *(const float4*)(xs + (size_t)(sr + rr * 16) * 64 + c4);
                px[rr] = make_uint2(pack2h(v.x, v.y), pack2h(v.z, v.w));
            }
        }

        float acc[4][4];
        #pragma unroll
        for (int s = 0; s < 4; s++)
            #pragma unroll
            for (int i = 0; i < 4; i++) acc[s][i] = 0.f;

        // ===== layer 0: acc = X * W0^T (4 k-chunks of 16) =====
        #pragma unroll
        for (int kc = 0; kc < 4; kc++) {
            const int kw = kc * 8 + tig;
            const uint32_t a0 = sX[(r0)     * SW + kw];
            const uint32_t a1 = sX[(r0 + 8) * SW + kw];
            const uint32_t a2 = sX[(r0)     * SW + kw + 4];
            const uint32_t a3 = sX[(r0 + 8) * SW + kw + 4];
            #pragma unroll
            for (int s = 0; s < 4; s++)
                mma_f16(acc[s][0], acc[s][1], acc[s][2], acc[s][3],
                        a0, a1, a2, a3, wf[0][s][kc][0], wf[0][s][kc][1]);
        }

        // epilogue 0: bias + LeakyReLU -> h (fp16) into sH
        #pragma unroll
        for (int s = 0; s < 4; s++) {
            const int jw = (jbase >> 1) + s * 4 + tig;
            float h00 = acc[s][0] + bf0[s][0]; h00 = (h00 > 0.f) ? h00 : 0.2f * h00;
            float h01 = acc[s][1] + bf0[s][1]; h01 = (h01 > 0.f) ? h01 : 0.2f * h01;
            float h10 = acc[s][2] + bf0[s][0]; h10 = (h10 > 0.f) ? h10 : 0.2f * h10;
            float h11 = acc[s][3] + bf0[s][1]; h11 = (h11 > 0.f) ? h11 : 0.2f * h11;
            sH[(r0)     * SW + jw] = pack2h(h00, h01);
            sH[(r0 + 8) * SW + jw] = pack2h(h10, h11);
        }
        __syncthreads();   // bar2: h visible; all L0 X-reads < storeX(t+1)

        // ===== layer 1: acc = h * W1^T =====
        #pragma unroll
        for (int s = 0; s < 4; s++)
            #pragma unroll
            for (int i = 0; i < 4; i++) acc[s][i] = 0.f;

        #pragma unroll
        for (int kc = 0; kc < 4; kc++) {
            const int kw = kc * 8 + tig;
            const uint32_t a0 = sH[(r0)     * SW + kw];
            const uint32_t a1 = sH[(r0 + 8) * SW + kw];
            const uint32_t a2 = sH[(r0)     * SW + kw + 4];
            const uint32_t a3 = sH[(r0 + 8) * SW + kw + 4];
            #pragma unroll
            for (int s = 0; s < 4; s++)
                mma_f16(acc[s][0], acc[s][1], acc[s][2], acc[s][3],
                        a0, a1, a2, a3, wf[1][s][kc][0], wf[1][s][kc][1]);
        }

        // epilogue 1: bias, 32B-sector float2 stores
        const int brow = it * 64 + r0;
        #pragma unroll
        for (int s = 0; s < 4; s++) {
            const int j = jbase + s * 8 + 2 * tig;
            float2 v0 = make_float2(acc[s][0] + bf1[s][0], acc[s][1] + bf1[s][1]);
            float2 v1 = make_float2(acc[s][2] + bf1[s][0], acc[s][3] + bf1[s][1]);
            *(float2*)(out + ((size_t)brow       * GROUPS + g) * 64 + j) = v0;
            *(float2*)(out + ((size_t)(brow + 8) * GROUPS + g) * 64 + j) = v1;
        }
    }
}

extern "C" void kernel_launch(void* const* d_in, const int* in_sizes, int n_in,
                              void* d_out, int out_size) {
    const float* x  = (const float*)d_in[0];
    const float* W0 = (const float*)d_in[1];
    const float* b0 = (const float*)d_in[2];
    const float* W1 = (const float*)d_in[3];
    const float* b1 = (const float*)d_in[4];
    float* out = (float*)d_out;

    convnn_r10<<<GROUPS, 256>>>(x, W0, b0, W1, b1, out);
}